// round 16
// baseline (speedup 1.0000x reference)
#include <cuda_runtime.h>
#include <cstdint>

#define NPIX (512*512)
#define NTIL 4096
#define FQ 0
#define FK 32768
#define FV 49152
#define FO 65536
#define QPM 0
#define BOS 66560
#define SMB 67072

__device__ uint32_t gB[24576];

typedef unsigned long long u64t;

__device__ __forceinline__ uint32_t s2u(const void*p){uint32_t a;asm("{.reg .u64 t; cvta.to.shared.u64 t,%1; cvt.u32.u64 %0,t;}":"=r"(a):"l"(p));return a;}
__device__ __forceinline__ uint32_t pkbf(float lo,float hi){uint32_t r;asm("cvt.rn.bf16x2.f32 %0,%1,%2;":"=r"(r):"f"(hi),"f"(lo));return r;}
__device__ __forceinline__ void split2(float x0,float x1,uint32_t&h,uint32_t&l){
  h=pkbf(x0,x1);
  float h0=__uint_as_float(h<<16),h1=__uint_as_float(h&0xffff0000u);
  l=pkbf(x0-h0,x1-h1);
}
__device__ __forceinline__ void upk2(u64t v,float&a,float&b){asm("mov.b64 {%0,%1},%2;":"=f"(a),"=f"(b):"l"(v));}
__device__ __forceinline__ u64t pk2(float v){u64t r;asm("mov.b64 %0,{%1,%1};":"=l"(r):"f"(v));return r;}
__device__ __forceinline__ void fma2(u64t&acc,u64t a,u64t b){asm("fma.rn.f32x2 %0,%1,%2,%0;":"+l"(acc):"l"(a),"l"(b));}
__device__ __forceinline__ void mmabf(float*d,const uint32_t*A,uint32_t b0,uint32_t b1){
  asm("mma.sync.aligned.m16n8k16.row.col.f32.bf16.bf16.f32 {%0,%1,%2,%3},{%4,%5,%6,%7},{%8,%9},{%0,%1,%2,%3};"
   :"+f"(d[0]),"+f"(d[1]),"+f"(d[2]),"+f"(d[3]):"r"(A[0]),"r"(A[1]),"r"(A[2]),"r"(A[3]),"r"(b0),"r"(b1));
}
__device__ __forceinline__ void mtrip(float*d,const uint32_t*Ah,const uint32_t*Al,uint4 b){
  mmabf(d,Ah,b.x,b.y); mmabf(d,Ah,b.z,b.w); mmabf(d,Al,b.x,b.y);
}
#define LDM(A,ad) asm volatile("ldmatrix.sync.aligned.m8n8.x4.shared.b16 {%0,%1,%2,%3},[%4];":"=r"((A)[0]),"=r"((A)[1]),"=r"((A)[2]),"=r"((A)[3]):"r"(ad))
__device__ __forceinline__ void ldAq(uint32_t base,uint32_t str,int R,int t5,int q0,uint32_t*A){
  int row=R+(t5&7)+((t5>>3)&1)*8;
  uint32_t ad=base+(uint32_t)row*str+(uint32_t)((q0+(t5>>4))<<5);
  LDM(A,ad);
}

__global__ void __launch_bounds__(512,1)
prep_kernel(const float* __restrict__ Wq,const float* __restrict__ Wk,
            const float* __restrict__ Wv_,const float* __restrict__ Wo)
{
  char* g=(char*)gB;
  const int tid=threadIdx.x;
  for(int i=tid;i<4096;i+=512){
    int ks=i>>9,rm=i&511,nt=rm>>6,rm2=rm&63,ln=rm2>>1,rg=rm2&1;
    int k=ks*16+rg*8+2*(ln&3),n=nt*8+(ln>>2);
    uint32_t h,l; split2(Wq[k*64+n]*0.25f,Wq[(k+1)*64+n]*0.25f,h,l);
    uint32_t fo=(uint32_t)(((ks*8+nt)*32+ln)<<4)+rg*4u;
    *(uint32_t*)(g+FQ+fo)=h; *(uint32_t*)(g+FQ+fo+8)=l;
  }
  for(int i=tid;i<2048;i+=512){
    int hh=i>>9,rm=i&511,nt=rm>>6,rm2=rm&63,ln=rm2>>1,rg=rm2&1;
    int d=rg*8+2*(ln&3),c=nt*8+(ln>>2);
    uint32_t h,l; split2(Wk[c*64+hh*16+d],Wk[c*64+hh*16+d+1],h,l);
    uint32_t fo=(uint32_t)(((hh*8+nt)*32+ln)<<4)+rg*4u;
    *(uint32_t*)(g+FK+fo)=h; *(uint32_t*)(g+FK+fo+8)=l;
  }
  for(int i=tid;i<2048;i+=512){
    int hh=i>>9,rm=i&511,ks=rm>>7,rm1=rm&127,nt=rm1>>6,rm2=rm1&63,ln=rm2>>1,rg=rm2&1;
    int k=ks*16+rg*8+2*(ln&3),j=nt*8+(ln>>2);
    uint32_t h,l; split2(Wv_[k*64+hh*16+j],Wv_[(k+1)*64+hh*16+j],h,l);
    uint32_t fo=(uint32_t)((((hh*4+ks)*2+nt)*32+ln)<<4)+rg*4u;
    *(uint32_t*)(g+FV+fo)=h; *(uint32_t*)(g+FV+fo+8)=l;
  }
  for(int i=tid;i<4096;i+=512){
    int kg=i>>10,rm=i&1023,nt=rm>>6,rm2=rm&63,ln=rm2>>1,rg=rm2&1;
    int k=kg*16+rg*8+2*(ln&3),n=nt*8+(ln>>2);
    uint32_t h,l; split2(Wo[k*128+n],Wo[(k+1)*128+n],h,l);
    uint32_t fo=(uint32_t)(((kg*16+nt)*32+ln)<<4)+rg*4u;
    *(uint32_t*)(g+FO+fo)=h; *(uint32_t*)(g+FO+fo+8)=l;
  }
}

__global__ void __launch_bounds__(256,2)
tpa_kernel(const float* __restrict__ t,const float* __restrict__ z,
           const float* __restrict__ mask,
           const float* __restrict__ bo,float* __restrict__ out,int ntiles)
{
  extern __shared__ char sm[];
  const uint32_t sb=s2u(sm);
  const char* g=(const char*)gB;
  const int tid=threadIdx.x,w=tid>>5,t5=tid&31,q=t5&3,r8=t5>>2;
  const int mtg=w>>2,nq=w&3,R=mtg*32;

  if(tid<128) ((float*)(sm+BOS))[tid]=bo[tid];
  const float bi0=1e5f*(mask[0]-1.f),bi1=1e5f*(mask[1]-1.f),
              bi2=1e5f*(mask[2]-1.f),bi3=1e5f*(mask[3]-1.f);
  __syncthreads();

  const int p8=tid>>3,u=tid&7;

  for(int tile=blockIdx.x;tile<ntiles;tile+=gridDim.x){
    const int n0=tile*64;
    // P1: z direct from global; warp owns M=32 rows x head nq (16 cols)
    float qacc[2][2][4]={};
    {
      const float* zb0=z+((size_t)(n0+R+r8))*128+2*q;
      const float* zb1=zb0+16*128;
      #pragma unroll
      for(int ks=0;ks<8;ks++){
        uint32_t Ah[2][4],Al[2][4];
        #pragma unroll
        for(int mi=0;mi<2;mi++){
          const float* p=(mi?zb1:zb0)+16*ks;
          float2 v0=*(const float2*)(p);
          float2 v1=*(const float2*)(p+8*128);
          float2 v2=*(const float2*)(p+8);
          float2 v3=*(const float2*)(p+8*128+8);
          split2(v0.x,v0.y,Ah[mi][0],Al[mi][0]);
          split2(v1.x,v1.y,Ah[mi][1],Al[mi][1]);
          split2(v2.x,v2.y,Ah[mi][2],Al[mi][2]);
          split2(v3.x,v3.y,Ah[mi][3],Al[mi][3]);
        }
        #pragma unroll
        for(int nt=0;nt<2;nt++){
          uint4 b=*(const uint4*)(g+FQ+(uint32_t)(((ks*8+nq*2+nt)*32+t5)<<4));
          mtrip(qacc[0][nt],Ah[0],Al[0],b);
          mtrip(qacc[1][nt],Ah[1],Al[1],b);
        }
      }
    }
    uint32_t QAh[2][4],QAl[2][4];
    #pragma unroll
    for(int mi=0;mi<2;mi++){
      split2(qacc[mi][0][0],qacc[mi][0][1],QAh[mi][0],QAl[mi][0]);
      split2(qacc[mi][0][2],qacc[mi][0][3],QAh[mi][1],QAl[mi][1]);
      split2(qacc[mi][1][0],qacc[mi][1][1],QAh[mi][2],QAl[mi][2]);
      split2(qacc[mi][1][2],qacc[mi][1][3],QAh[mi][3],QAl[mi][3]);
    }
    // P2: Qp (head nq) fp32 -> QPM + px*1040 + nq*256 (own rows/cols)
    #pragma unroll
    for(int nt=0;nt<8;nt++){
      uint4 b=*(const uint4*)(g+FK+(uint32_t)(((nq*8+nt)*32+t5)<<4));
      #pragma unroll
      for(int mi=0;mi<2;mi++){
        float a[4]={};
        mtrip(a,QAh[mi],QAl[mi],b);
        uint32_t o=(uint32_t)(nq*256+nt*32+q*8);
        *(float2*)(sm+QPM+(uint32_t)(R+16*mi+r8)*1040u+o)=make_float2(a[0],a[1]);
        *(float2*)(sm+QPM+(uint32_t)(R+16*mi+r8+8)*1040u+o)=make_float2(a[2],a[3]);
      }
    }
    __syncthreads();
    // P3: logits+softmax+m (in place), 8 thr/px, 2 passes of 32 px
    #pragma unroll
    for(int it=0;it<2;it++){
      const int px=it*32+p8,c0=u*8; const size_t ng=(size_t)n0+px;
      u64t tv[4][4];
      #pragma unroll
      for(int tt=0;tt<4;tt++){
        const float4* tp=(const float4*)(t+((size_t)tt*NPIX+ng)*64+c0);
        float4 v0=tp[0],v1=tp[1];
        tv[tt][0]=*(u64t*)&v0.x; tv[tt][1]=*(u64t*)&v0.z;
        tv[tt][2]=*(u64t*)&v1.x; tv[tt][3]=*(u64t*)&v1.z;
      }
      char* qpc=sm+QPM+(size_t)px*1040+u*32;
      float lg[4][4];
      #pragma unroll
      for(int h=0;h<4;h++){
        ulonglong2 qa=*(const ulonglong2*)(qpc+h*256),qb=*(const ulonglong2*)(qpc+h*256+16);
        #pragma unroll
        for(int tt=0;tt<4;tt++){
          u64t s=0;
          fma2(s,qa.x,tv[tt][0]); fma2(s,qa.y,tv[tt][1]);
          fma2(s,qb.x,tv[tt][2]); fma2(s,qb.y,tv[tt][3]);
          float x0,x1; upk2(s,x0,x1); lg[h][tt]=x0+x1;
        }
      }
      #pragma unroll
      for(int off=4;off>=1;off>>=1)
        #pragma unroll
        for(int h=0;h<4;h++)
          #pragma unroll
          for(int tt=0;tt<4;tt++)
            lg[h][tt]+=__shfl_xor_sync(0xffffffffu,lg[h][tt],off,8);
      #pragma unroll
      for(int h=0;h<4;h++){
        float l0=lg[h][0]+bi0,l1=lg[h][1]+bi1,l2=lg[h][2]+bi2,l3=lg[h][3]+bi3;
        float mx=fmaxf(fmaxf(l0,l1),fmaxf(l2,l3));
        float e0=__expf(l0-mx),e1=__expf(l1-mx),e2=__expf(l2-mx),e3=__expf(l3-mx);
        float inv=1.0f/(e0+e1+e2+e3);
        u64t a0=pk2(e0*inv),a1=pk2(e1*inv),a2=pk2(e2*inv),a3=pk2(e3*inv);
        u64t mm[4]={0,0,0,0};
        #pragma unroll
        for(int j=0;j<4;j++){
          fma2(mm[j],a0,tv[0][j]); fma2(mm[j],a1,tv[1][j]);
          fma2(mm[j],a2,tv[2][j]); fma2(mm[j],a3,tv[3][j]);
        }
        uint32_t hw[4],lw[4];
        #pragma unroll
        for(int j=0;j<4;j++){float x0,x1; upk2(mm[j],x0,x1); split2(x0,x1,hw[j],lw[j]);}
        *(uint4*)(qpc+h*256)=make_uint4(hw[0],hw[1],hw[2],hw[3]);
        *(uint4*)(qpc+h*256+16)=make_uint4(lw[0],lw[1],lw[2],lw[3]);
      }
    }
    __syncthreads();
    // P4: m(mtg rows, head nq) @ Wv_nq -> O frags
    float oa[2][2][4]={};
    #pragma unroll
    for(int ks=0;ks<4;ks++){
      uint32_t Ah[2][4],Al[2][4];
      #pragma unroll
      for(int mi=0;mi<2;mi++){
        ldAq(sb+QPM+(uint32_t)(nq*256),1040u,R+16*mi,t5,2*ks,Ah[mi]);
        ldAq(sb+QPM+(uint32_t)(nq*256+16),1040u,R+16*mi,t5,2*ks,Al[mi]);
      }
      #pragma unroll
      for(int nt=0;nt<2;nt++){
        uint4 b=*(const uint4*)(g+FV+(uint32_t)((((nq*4+ks)*2+nt)*32+t5)<<4));
        mtrip(oa[0][nt],Ah[0],Al[0],b);
        mtrip(oa[1][nt],Ah[1],Al[1],b);
      }
    }
    // group barrier: all 4 nq warps of this mtg done reading m
    asm volatile("bar.sync %0,%1;"::"r"(1+mtg),"r"(128):"memory");
    // O store overlaid on cols 0..271 of own rows (slot = nq*2+nt)
    #pragma unroll
    for(int mi=0;mi<2;mi++)
      #pragma unroll
      for(int nt=0;nt<2;nt++){
        uint32_t h0,l0,h1,l1;
        split2(oa[mi][nt][0],oa[mi][nt][1],h0,l0);
        split2(oa[mi][nt][2],oa[mi][nt][3],h1,l1);
        uint32_t o=(uint32_t)((nq*2+nt)*32+q*4);
        char* b0p=sm+QPM+(size_t)(R+16*mi+r8)*1040+o;
        char* b1p=sm+QPM+(size_t)(R+16*mi+r8+8)*1040+o;
        *(uint32_t*)b0p=h0; *(uint32_t*)(b0p+16)=l0;
        *(uint32_t*)b1p=h1; *(uint32_t*)(b1p+16)=l1;
      }
    asm volatile("bar.sync %0,%1;"::"r"(1+mtg),"r"(128):"memory");
    // P5: O(group rows) @ Wo[:, nq*32..] -> out regs
    float acc5[2][4][4]={};
    #pragma unroll
    for(int ks=0;ks<4;ks++){
      uint32_t Ah[2][4],Al[2][4];
      #pragma unroll
      for(int mi=0;mi<2;mi++){
        ldAq(sb+QPM,1040u,R+16*mi,t5,2*ks,Ah[mi]);
        ldAq(sb+QPM+16u,1040u,R+16*mi,t5,2*ks,Al[mi]);
      }
      #pragma unroll
      for(int nt=0;nt<4;nt++){
        uint4 b=*(const uint4*)(g+FO+(uint32_t)(((ks*16+nq*4+nt)*32+t5)<<4));
        mtrip(acc5[0][nt],Ah[0],Al[0],b);
        mtrip(acc5[1][nt],Ah[1],Al[1],b);
      }
    }
    // group barrier: O reads done before next tile's P2 overwrites these rows
    asm volatile("bar.sync %0,%1;"::"r"(1+mtg),"r"(128):"memory");
    #pragma unroll
    for(int mi=0;mi<2;mi++)
      #pragma unroll
      for(int nt=0;nt<4;nt++){
        int c=nq*32+nt*8+2*q;
        float2 b=*(const float2*)(sm+BOS+(uint32_t)c*4u);
        float* o0=out+((size_t)(n0+R+16*mi+r8))*128+c;
        *(float2*)o0=make_float2(acc5[mi][nt][0]+b.x,acc5[mi][nt][1]+b.y);
        *(float2*)(o0+8*128)=make_float2(acc5[mi][nt][2]+b.x,acc5[mi][nt][3]+b.y);
      }
  }
}

extern "C" void kernel_launch(void* const* d_in,const int* in_sizes,int n_in,
                              void* d_out,int out_size)
{
  const float* t  =(const float*)d_in[0];
  const float* z  =(const float*)d_in[1];
  const float* mk =(const float*)d_in[2];
  const float* wq =(const float*)d_in[3];
  const float* wk =(const float*)d_in[4];
  const float* wv =(const float*)d_in[5];
  const float* wo =(const float*)d_in[6];
  const float* bo =(const float*)d_in[7];
  float* out=(float*)d_out;
  int nsm=148;
  cudaDeviceGetAttribute(&nsm,cudaDevAttrMultiProcessorCount,0);
  cudaFuncSetAttribute(tpa_kernel,cudaFuncAttributeMaxDynamicSharedMemorySize,SMB);
  prep_kernel<<<1,512>>>(wq,wk,wv,wo);
  int grid=2*nsm; if(grid>NTIL) grid=NTIL;
  tpa_kernel<<<grid,256,SMB>>>(t,z,mk,bo,out,NTIL);
}

// round 17
// speedup vs baseline: 1.0898x; 1.0898x over previous
#include <cuda_runtime.h>
#include <cstdint>

#define NPIX (512*512)
#define NTIL 4096
#define FQ 0
#define FK 32768
#define FV 49152
#define FO 65536
#define QPM 0
#define BOS 66560
#define SMB 67072

__device__ uint32_t gB[24576];

typedef unsigned long long u64t;

__device__ __forceinline__ uint32_t s2u(const void*p){uint32_t a;asm("{.reg .u64 t; cvta.to.shared.u64 t,%1; cvt.u32.u64 %0,t;}":"=r"(a):"l"(p));return a;}
__device__ __forceinline__ uint32_t pkbf(float lo,float hi){uint32_t r;asm("cvt.rn.bf16x2.f32 %0,%1,%2;":"=r"(r):"f"(hi),"f"(lo));return r;}
__device__ __forceinline__ void split2(float x0,float x1,uint32_t&h,uint32_t&l){
  h=pkbf(x0,x1);
  float h0=__uint_as_float(h<<16),h1=__uint_as_float(h&0xffff0000u);
  l=pkbf(x0-h0,x1-h1);
}
__device__ __forceinline__ void upk2(u64t v,float&a,float&b){asm("mov.b64 {%0,%1},%2;":"=f"(a),"=f"(b):"l"(v));}
__device__ __forceinline__ u64t pk2(float v){u64t r;asm("mov.b64 %0,{%1,%1};":"=l"(r):"f"(v));return r;}
__device__ __forceinline__ void fma2(u64t&acc,u64t a,u64t b){asm("fma.rn.f32x2 %0,%1,%2,%0;":"+l"(acc):"l"(a),"l"(b));}
__device__ __forceinline__ void mmabf(float*d,const uint32_t*A,uint32_t b0,uint32_t b1){
  asm("mma.sync.aligned.m16n8k16.row.col.f32.bf16.bf16.f32 {%0,%1,%2,%3},{%4,%5,%6,%7},{%8,%9},{%0,%1,%2,%3};"
   :"+f"(d[0]),"+f"(d[1]),"+f"(d[2]),"+f"(d[3]):"r"(A[0]),"r"(A[1]),"r"(A[2]),"r"(A[3]),"r"(b0),"r"(b1));
}
__device__ __forceinline__ void mtrip(float*d,const uint32_t*Ah,const uint32_t*Al,uint4 b){
  mmabf(d,Ah,b.x,b.y); mmabf(d,Ah,b.z,b.w); mmabf(d,Al,b.x,b.y);
}
#define LDM(A,ad) asm volatile("ldmatrix.sync.aligned.m8n8.x4.shared.b16 {%0,%1,%2,%3},[%4];":"=r"((A)[0]),"=r"((A)[1]),"=r"((A)[2]),"=r"((A)[3]):"r"(ad))
__device__ __forceinline__ void ldAq(uint32_t base,uint32_t str,int R,int t5,int q0,uint32_t*A){
  int row=R+(t5&7)+((t5>>3)&1)*8;
  uint32_t ad=base+(uint32_t)row*str+(uint32_t)((q0+(t5>>4))<<5);
  LDM(A,ad);
}

__global__ void __launch_bounds__(256,1)
prep_kernel(const float* __restrict__ Wq,const float* __restrict__ Wk,
            const float* __restrict__ Wv_,const float* __restrict__ Wo)
{
  char* g=(char*)gB;
  const int gt=blockIdx.x*256+threadIdx.x, NT=gridDim.x*256;
  for(int i=gt;i<4096;i+=NT){
    int ks=i>>9,rm=i&511,nt=rm>>6,rm2=rm&63,ln=rm2>>1,rg=rm2&1;
    int k=ks*16+rg*8+2*(ln&3),n=nt*8+(ln>>2);
    uint32_t h,l; split2(Wq[k*64+n]*0.25f,Wq[(k+1)*64+n]*0.25f,h,l);
    uint32_t fo=(uint32_t)(((ks*8+nt)*32+ln)<<4)+rg*4u;
    *(uint32_t*)(g+FQ+fo)=h; *(uint32_t*)(g+FQ+fo+8)=l;
  }
  for(int i=gt;i<2048;i+=NT){
    int hh=i>>9,rm=i&511,nt=rm>>6,rm2=rm&63,ln=rm2>>1,rg=rm2&1;
    int d=rg*8+2*(ln&3),c=nt*8+(ln>>2);
    uint32_t h,l; split2(Wk[c*64+hh*16+d],Wk[c*64+hh*16+d+1],h,l);
    uint32_t fo=(uint32_t)(((hh*8+nt)*32+ln)<<4)+rg*4u;
    *(uint32_t*)(g+FK+fo)=h; *(uint32_t*)(g+FK+fo+8)=l;
  }
  for(int i=gt;i<2048;i+=NT){
    int hh=i>>9,rm=i&511,ks=rm>>7,rm1=rm&127,nt=rm1>>6,rm2=rm1&63,ln=rm2>>1,rg=rm2&1;
    int k=ks*16+rg*8+2*(ln&3),j=nt*8+(ln>>2);
    uint32_t h,l; split2(Wv_[k*64+hh*16+j],Wv_[(k+1)*64+hh*16+j],h,l);
    uint32_t fo=(uint32_t)((((hh*4+ks)*2+nt)*32+ln)<<4)+rg*4u;
    *(uint32_t*)(g+FV+fo)=h; *(uint32_t*)(g+FV+fo+8)=l;
  }
  for(int i=gt;i<4096;i+=NT){
    int kg=i>>10,rm=i&1023,nt=rm>>6,rm2=rm&63,ln=rm2>>1,rg=rm2&1;
    int k=kg*16+rg*8+2*(ln&3),n=nt*8+(ln>>2);
    uint32_t h,l; split2(Wo[k*128+n],Wo[(k+1)*128+n],h,l);
    uint32_t fo=(uint32_t)(((kg*16+nt)*32+ln)<<4)+rg*4u;
    *(uint32_t*)(g+FO+fo)=h; *(uint32_t*)(g+FO+fo+8)=l;
  }
}

__global__ void __launch_bounds__(128,3)
tpa_kernel(const float* __restrict__ t,const float* __restrict__ z,
           const float* __restrict__ mask,
           const float* __restrict__ bo,float* __restrict__ out,int ntiles)
{
  extern __shared__ char sm[];
  const uint32_t sb=s2u(sm);
  const char* g=(const char*)gB;
  const int tid=threadIdx.x,w=tid>>5,t5=tid&31,q=t5&3,r8=t5>>2;
  const int mtg=w>>1,nh=w&1,R=mtg*32;

  if(tid<128) ((float*)(sm+BOS))[tid]=bo[tid];
  const float bi0=1e5f*(mask[0]-1.f),bi1=1e5f*(mask[1]-1.f),
              bi2=1e5f*(mask[2]-1.f),bi3=1e5f*(mask[3]-1.f);
  __syncthreads();

  const int p8=tid>>3,u=tid&7;

  for(int tile=blockIdx.x;tile<ntiles;tile+=gridDim.x){
    const int n0=tile*64;
    // P1: z direct from global; Q in regs; M=32 per warp (2 m-tiles)
    float qacc[2][4][4]={};
    {
      const float* zb0=z+((size_t)(n0+R+r8))*128+2*q;
      const float* zb1=zb0+16*128;
      #pragma unroll
      for(int ks=0;ks<8;ks++){
        uint32_t Ah[2][4],Al[2][4];
        #pragma unroll
        for(int mi=0;mi<2;mi++){
          const float* p=(mi?zb1:zb0)+16*ks;
          float2 v0=*(const float2*)(p);
          float2 v1=*(const float2*)(p+8*128);
          float2 v2=*(const float2*)(p+8);
          float2 v3=*(const float2*)(p+8*128+8);
          split2(v0.x,v0.y,Ah[mi][0],Al[mi][0]);
          split2(v1.x,v1.y,Ah[mi][1],Al[mi][1]);
          split2(v2.x,v2.y,Ah[mi][2],Al[mi][2]);
          split2(v3.x,v3.y,Ah[mi][3],Al[mi][3]);
        }
        #pragma unroll
        for(int nt=0;nt<4;nt++){
          uint4 b=*(const uint4*)(g+FQ+(uint32_t)(((ks*8+nh*4+nt)*32+t5)<<4));
          mtrip(qacc[0][nt],Ah[0],Al[0],b);
          mtrip(qacc[1][nt],Ah[1],Al[1],b);
        }
      }
    }
    uint32_t QAh[2][2][4],QAl[2][2][4];
    #pragma unroll
    for(int mi=0;mi<2;mi++)
      #pragma unroll
      for(int hh=0;hh<2;hh++){
        split2(qacc[mi][2*hh][0],qacc[mi][2*hh][1],QAh[mi][hh][0],QAl[mi][hh][0]);
        split2(qacc[mi][2*hh][2],qacc[mi][2*hh][3],QAh[mi][hh][1],QAl[mi][hh][1]);
        split2(qacc[mi][2*hh+1][0],qacc[mi][2*hh+1][1],QAh[mi][hh][2],QAl[mi][hh][2]);
        split2(qacc[mi][2*hh+1][2],qacc[mi][2*hh+1][3],QAh[mi][hh][3],QAl[mi][hh][3]);
      }
    // P2: Qp fp32 -> QPM + px*1040 + h*256 (own rows, own head cols)
    #pragma unroll
    for(int hh=0;hh<2;hh++){
      const int h=2*nh+hh;
      #pragma unroll
      for(int nt=0;nt<8;nt++){
        uint4 b=*(const uint4*)(g+FK+(uint32_t)(((h*8+nt)*32+t5)<<4));
        #pragma unroll
        for(int mi=0;mi<2;mi++){
          float a[4]={};
          mtrip(a,QAh[mi][hh],QAl[mi][hh],b);
          uint32_t o=(uint32_t)(h*256+nt*32+q*8);
          *(float2*)(sm+QPM+(uint32_t)(R+16*mi+r8)*1040u+o)=make_float2(a[0],a[1]);
          *(float2*)(sm+QPM+(uint32_t)(R+16*mi+r8+8)*1040u+o)=make_float2(a[2],a[3]);
        }
      }
    }
    __syncthreads();
    // P3: logits+softmax+m (in place), 8 thr/px, 4 passes of 16 px
    #pragma unroll
    for(int it=0;it<4;it++){
      const int px=it*16+p8,c0=u*8; const size_t ng=(size_t)n0+px;
      u64t tv[4][4];
      #pragma unroll
      for(int tt=0;tt<4;tt++){
        const float4* tp=(const float4*)(t+((size_t)tt*NPIX+ng)*64+c0);
        float4 v0=tp[0],v1=tp[1];
        tv[tt][0]=*(u64t*)&v0.x; tv[tt][1]=*(u64t*)&v0.z;
        tv[tt][2]=*(u64t*)&v1.x; tv[tt][3]=*(u64t*)&v1.z;
      }
      char* qpc=sm+QPM+(size_t)px*1040+u*32;
      float lg[4][4];
      #pragma unroll
      for(int h=0;h<4;h++){
        ulonglong2 qa=*(const ulonglong2*)(qpc+h*256),qb=*(const ulonglong2*)(qpc+h*256+16);
        #pragma unroll
        for(int tt=0;tt<4;tt++){
          u64t s=0;
          fma2(s,qa.x,tv[tt][0]); fma2(s,qa.y,tv[tt][1]);
          fma2(s,qb.x,tv[tt][2]); fma2(s,qb.y,tv[tt][3]);
          float x0,x1; upk2(s,x0,x1); lg[h][tt]=x0+x1;
        }
      }
      #pragma unroll
      for(int off=4;off>=1;off>>=1)
        #pragma unroll
        for(int h=0;h<4;h++)
          #pragma unroll
          for(int tt=0;tt<4;tt++)
            lg[h][tt]+=__shfl_xor_sync(0xffffffffu,lg[h][tt],off,8);
      #pragma unroll
      for(int h=0;h<4;h++){
        float l0=lg[h][0]+bi0,l1=lg[h][1]+bi1,l2=lg[h][2]+bi2,l3=lg[h][3]+bi3;
        float mx=fmaxf(fmaxf(l0,l1),fmaxf(l2,l3));
        float e0=__expf(l0-mx),e1=__expf(l1-mx),e2=__expf(l2-mx),e3=__expf(l3-mx);
        float inv=1.0f/(e0+e1+e2+e3);
        u64t a0=pk2(e0*inv),a1=pk2(e1*inv),a2=pk2(e2*inv),a3=pk2(e3*inv);
        u64t mm[4]={0,0,0,0};
        #pragma unroll
        for(int j=0;j<4;j++){
          fma2(mm[j],a0,tv[0][j]); fma2(mm[j],a1,tv[1][j]);
          fma2(mm[j],a2,tv[2][j]); fma2(mm[j],a3,tv[3][j]);
        }
        uint32_t hw[4],lw[4];
        #pragma unroll
        for(int j=0;j<4;j++){float x0,x1; upk2(mm[j],x0,x1); split2(x0,x1,hw[j],lw[j]);}
        *(uint4*)(qpc+h*256)=make_uint4(hw[0],hw[1],hw[2],hw[3]);
        *(uint4*)(qpc+h*256+16)=make_uint4(lw[0],lw[1],lw[2],lw[3]);
      }
    }
    __syncthreads();
    // P4: m(mtg rows) @ Wv -> O frags
    float oa[2][2][2][4]={};
    #pragma unroll
    for(int hh=0;hh<2;hh++){
      const int h=2*nh+hh;
      #pragma unroll
      for(int ks=0;ks<4;ks++){
        uint32_t Ah[2][4],Al[2][4];
        #pragma unroll
        for(int mi=0;mi<2;mi++){
          ldAq(sb+QPM+(uint32_t)(h*256),1040u,R+16*mi,t5,2*ks,Ah[mi]);
          ldAq(sb+QPM+(uint32_t)(h*256+16),1040u,R+16*mi,t5,2*ks,Al[mi]);
        }
        #pragma unroll
        for(int nt=0;nt<2;nt++){
          uint4 b=*(const uint4*)(g+FV+(uint32_t)((((h*4+ks)*2+nt)*32+t5)<<4));
          mtrip(oa[0][hh][nt],Ah[0],Al[0],b);
          mtrip(oa[1][hh][nt],Ah[1],Al[1],b);
        }
      }
    }
    // group barrier: both nh warps done reading m of these rows
    asm volatile("bar.sync %0,%1;"::"r"(1+mtg),"r"(64):"memory");
    // O store overlaid on cols 0..271 of own rows
    #pragma unroll
    for(int mi=0;mi<2;mi++)
      #pragma unroll
      for(int hh=0;hh<2;hh++){
        const int h=2*nh+hh;
        #pragma unroll
        for(int nt=0;nt<2;nt++){
          uint32_t h0,l0,h1,l1;
          split2(oa[mi][hh][nt][0],oa[mi][hh][nt][1],h0,l0);
          split2(oa[mi][hh][nt][2],oa[mi][hh][nt][3],h1,l1);
          uint32_t o=(uint32_t)((h*2+nt)*32+q*4);
          char* b0p=sm+QPM+(size_t)(R+16*mi+r8)*1040+o;
          char* b1p=sm+QPM+(size_t)(R+16*mi+r8+8)*1040+o;
          *(uint32_t*)b0p=h0; *(uint32_t*)(b0p+16)=l0;
          *(uint32_t*)b1p=h1; *(uint32_t*)(b1p+16)=l1;
        }
      }
    asm volatile("bar.sync %0,%1;"::"r"(1+mtg),"r"(64):"memory");
    // P5: O(group rows) @ Wo -> out regs
    float acc5[2][8][4]={};
    #pragma unroll
    for(int ks=0;ks<4;ks++){
      uint32_t Ah[2][4],Al[2][4];
      #pragma unroll
      for(int mi=0;mi<2;mi++){
        ldAq(sb+QPM,1040u,R+16*mi,t5,2*ks,Ah[mi]);
        ldAq(sb+QPM+16u,1040u,R+16*mi,t5,2*ks,Al[mi]);
      }
      #pragma unroll
      for(int nt=0;nt<8;nt++){
        uint4 b=*(const uint4*)(g+FO+(uint32_t)(((ks*16+nh*8+nt)*32+t5)<<4));
        mtrip(acc5[0][nt],Ah[0],Al[0],b);
        mtrip(acc5[1][nt],Ah[1],Al[1],b);
      }
    }
    // group barrier: O reads done before next tile's P2 overwrites these rows
    asm volatile("bar.sync %0,%1;"::"r"(1+mtg),"r"(64):"memory");
    #pragma unroll
    for(int mi=0;mi<2;mi++)
      #pragma unroll
      for(int nt=0;nt<8;nt++){
        int c=nh*64+nt*8+2*q;
        float2 b=*(const float2*)(sm+BOS+(uint32_t)c*4u);
        float* o0=out+((size_t)(n0+R+16*mi+r8))*128+c;
        *(float2*)o0=make_float2(acc5[mi][nt][0]+b.x,acc5[mi][nt][1]+b.y);
        *(float2*)(o0+8*128)=make_float2(acc5[mi][nt][2]+b.x,acc5[mi][nt][3]+b.y);
      }
  }
}

extern "C" void kernel_launch(void* const* d_in,const int* in_sizes,int n_in,
                              void* d_out,int out_size)
{
  const float* t  =(const float*)d_in[0];
  const float* z  =(const float*)d_in[1];
  const float* mk =(const float*)d_in[2];
  const float* wq =(const float*)d_in[3];
  const float* wk =(const float*)d_in[4];
  const float* wv =(const float*)d_in[5];
  const float* wo =(const float*)d_in[6];
  const float* bo =(const float*)d_in[7];
  float* out=(float*)d_out;
  int nsm=148;
  cudaDeviceGetAttribute(&nsm,cudaDevAttrMultiProcessorCount,0);
  cudaFuncSetAttribute(tpa_kernel,cudaFuncAttributeMaxDynamicSharedMemorySize,SMB);
  prep_kernel<<<48,256>>>(wq,wk,wv,wo);
  int grid=3*nsm; if(grid>NTIL) grid=NTIL;
  tpa_kernel<<<grid,128,SMB>>>(t,z,mk,bo,out,NTIL);
}